// round 9
// baseline (speedup 1.0000x reference)
#include <cuda_runtime.h>
#include <cuda_bf16.h>
#include <mma.h>
#include <math.h>

using namespace nvcuda;

// Problem constants (fixed shapes)
#define BSZ   4
#define SEQ   1024
#define DM    512
#define NH    8
#define DQ    64
#define M_TOT (BSZ*SEQ)     // 4096 tokens
#define NBH   (BSZ*NH)      // 32 (batch,head) pairs
#define NTILE 32            // token tiles of 128

// -------------------- device scratch --------------------
__device__ float g_Sf[NBH * SEQ];          // forward scores  s(i,i+1)/512
__device__ float g_Sb[NBH * SEQ];          // backward scores s(i,i-1)/512
__device__ float g_G [NBH * SEQ];          // exclusive prefix sums of g
__device__ float g_band[NBH * SEQ];        // ph_i
// halo: biased q/k vectors at tile edges, [head][tile][64]
__device__ float g_qF[NH * NTILE * DQ];
__device__ float g_qL[NH * NTILE * DQ];
__device__ float g_kF[NH * NTILE * DQ];
__device__ float g_kL[NH * NTILE * DQ];

// -------------------- Kernel 1: fused GEMM + banded-dot epilogue ---------------
// Block (h, m): C[128 tokens of tile m][ Qh feats 0..63 | Kh feats 64..127 ]
#define BM   128
#define BN   128
#define BKK  32
#define KPAD 40
#define CLD  132                     // C staging row stride (floats)
#define SMEM_AS_BYTES  (2*BM*KPAD*2) // 20480
#define SMEM_CST_BYTES (BM*CLD*4)    // 67584
#define SMEM_TOTAL_GEMM (SMEM_CST_BYTES + 512)

__global__ __launch_bounds__(256) void gemm_band_kernel(
    const float* __restrict__ ctx,
    const float* __restrict__ Wq,
    const float* __restrict__ Wk,
    const float* __restrict__ bq,
    const float* __restrict__ bk)
{
    extern __shared__ char dsm[];
    __nv_bfloat16 (*As)[BM][KPAD] = (__nv_bfloat16(*)[BM][KPAD])dsm;
    __nv_bfloat16 (*Bs)[BM][KPAD] = (__nv_bfloat16(*)[BM][KPAD])(dsm + SMEM_AS_BYTES);
    float (*Cst)[CLD] = (float(*)[CLD])dsm;                 // reuses As/Bs after MMAs
    float* bqs = (float*)(dsm + SMEM_CST_BYTES);
    float* bks = bqs + DQ;

    const int h  = blockIdx.x;           // head 0..7
    const int m  = blockIdx.y;           // token tile 0..31
    const int tid = threadIdx.x;
    const int warp = tid >> 5;
    const int lane = tid & 31;
    const int wm = warp & 3;
    const int wn = warp >> 2;

    // load head-sliced biases
    if (tid < DQ)        bqs[tid] = bq[h*DQ + tid];
    else if (tid < 2*DQ) bks[tid - DQ] = bk[h*DQ + (tid - DQ)];

    wmma::fragment<wmma::accumulator,16,16,16,float> acc[2][4];
    #pragma unroll
    for (int mm = 0; mm < 2; mm++)
        #pragma unroll
        for (int nn = 0; nn < 4; nn++)
            wmma::fill_fragment(acc[mm][nn], 0.0f);

    // per-thread load coords: 4 float4-groups for A, 4 for B
    int rowL[4], gcL[4];
    const float* srcB[4];
    #pragma unroll
    for (int j = 0; j < 4; j++) {
        int idx = tid + 256 * j;         // 1024 groups per tile
        rowL[j] = idx >> 3;
        gcL[j]  = (idx & 7) * 4;
        int r = rowL[j];
        srcB[j] = (r < DQ) ? &Wq[(size_t)(h*DQ + r)*DM]
                           : &Wk[(size_t)(h*DQ + r - DQ)*DM];
    }
    const float* srcA = &ctx[(size_t)(m*BM)*DM];

    // preload tile 0
    #pragma unroll
    for (int j = 0; j < 4; j++) {
        float4 va = *(const float4*)&srcA[(size_t)rowL[j]*DM + gcL[j]];
        As[0][rowL[j]][gcL[j]+0] = __float2bfloat16(va.x);
        As[0][rowL[j]][gcL[j]+1] = __float2bfloat16(va.y);
        As[0][rowL[j]][gcL[j]+2] = __float2bfloat16(va.z);
        As[0][rowL[j]][gcL[j]+3] = __float2bfloat16(va.w);
        float4 vb = *(const float4*)&srcB[j][gcL[j]];
        Bs[0][rowL[j]][gcL[j]+0] = __float2bfloat16(vb.x);
        Bs[0][rowL[j]][gcL[j]+1] = __float2bfloat16(vb.y);
        Bs[0][rowL[j]][gcL[j]+2] = __float2bfloat16(vb.z);
        Bs[0][rowL[j]][gcL[j]+3] = __float2bfloat16(vb.w);
    }
    __syncthreads();

    const int NIT = DM / BKK;            // 16
    for (int kt = 0; kt < NIT; kt++) {
        const int cur = kt & 1;
        float4 av[4], bv[4];
        if (kt + 1 < NIT) {
            const int kg = (kt + 1) * BKK;
            #pragma unroll
            for (int j = 0; j < 4; j++) {
                av[j] = *(const float4*)&srcA[(size_t)rowL[j]*DM + kg + gcL[j]];
                bv[j] = *(const float4*)&srcB[j][kg + gcL[j]];
            }
        }

        #pragma unroll
        for (int kk = 0; kk < BKK; kk += 16) {
            wmma::fragment<wmma::matrix_a,16,16,16,__nv_bfloat16,wmma::row_major> af[2];
            wmma::fragment<wmma::matrix_b,16,16,16,__nv_bfloat16,wmma::col_major> bf[4];
            #pragma unroll
            for (int mm = 0; mm < 2; mm++)
                wmma::load_matrix_sync(af[mm], &As[cur][wm*32 + mm*16][kk], KPAD);
            #pragma unroll
            for (int nn = 0; nn < 4; nn++)
                wmma::load_matrix_sync(bf[nn], &Bs[cur][wn*64 + nn*16][kk], KPAD);
            #pragma unroll
            for (int mm = 0; mm < 2; mm++)
                #pragma unroll
                for (int nn = 0; nn < 4; nn++)
                    wmma::mma_sync(acc[mm][nn], af[mm], bf[nn], acc[mm][nn]);
        }

        if (kt + 1 < NIT) {
            const int nxt = cur ^ 1;
            #pragma unroll
            for (int j = 0; j < 4; j++) {
                As[nxt][rowL[j]][gcL[j]+0] = __float2bfloat16(av[j].x);
                As[nxt][rowL[j]][gcL[j]+1] = __float2bfloat16(av[j].y);
                As[nxt][rowL[j]][gcL[j]+2] = __float2bfloat16(av[j].z);
                As[nxt][rowL[j]][gcL[j]+3] = __float2bfloat16(av[j].w);
                Bs[nxt][rowL[j]][gcL[j]+0] = __float2bfloat16(bv[j].x);
                Bs[nxt][rowL[j]][gcL[j]+1] = __float2bfloat16(bv[j].y);
                Bs[nxt][rowL[j]][gcL[j]+2] = __float2bfloat16(bv[j].z);
                Bs[nxt][rowL[j]][gcL[j]+3] = __float2bfloat16(bv[j].w);
            }
        }
        __syncthreads();
    }

    // ---- stage C into smem (overwrites As/Bs; all MMAs done, accs in regs) ----
    #pragma unroll
    for (int mm = 0; mm < 2; mm++)
        #pragma unroll
        for (int nn = 0; nn < 4; nn++)
            wmma::store_matrix_sync(&Cst[wm*32 + mm*16][wn*64 + nn*16],
                                    acc[mm][nn], CLD, wmma::mem_row_major);
    __syncthreads();

    // ---- halo: biased q/k vectors at tile edges ----
    if (tid < DQ) {
        int d = tid;
        int hm = (h*NTILE + m)*DQ + d;
        g_qF[hm] = Cst[0][d]        + bqs[d];
        g_kF[hm] = Cst[0][DQ + d]   + bks[d];
        g_qL[hm] = Cst[127][d]      + bqs[d];
        g_kL[hm] = Cst[127][DQ + d] + bks[d];
    }

    // ---- interior banded dots: warp w handles rows w*16 .. w*16+15 ----
    const int d = lane * 2;
    float2 bqv = *(float2*)&bqs[d];
    float2 bkv = *(float2*)&bks[d];
    #pragma unroll
    for (int rr = 0; rr < 16; rr++) {
        int r = warp*16 + rr;
        float2 qv = *(float2*)&Cst[r][d];
        float q0 = qv.x + bqv.x, q1 = qv.y + bqv.y;
        float sf = 0.f, sb = 0.f;
        if (r < 127) {
            float2 kv = *(float2*)&Cst[r+1][DQ + d];
            sf = q0*(kv.x + bkv.x) + q1*(kv.y + bkv.y);
        }
        if (r > 0) {
            float2 kv = *(float2*)&Cst[r-1][DQ + d];
            sb = q0*(kv.x + bkv.x) + q1*(kv.y + bkv.y);
        }
        #pragma unroll
        for (int off = 16; off; off >>= 1) {
            sf += __shfl_down_sync(0xffffffffu, sf, off);
            sb += __shfl_down_sync(0xffffffffu, sb, off);
        }
        if (lane == 0) {
            int row = m*BM + r;
            int b = row >> 10;
            int i = row & (SEQ - 1);
            int idx = (b*NH + h)*SEQ + i;
            if (r < 127) g_Sf[idx] = sf * (1.0f / DM);
            if (r > 0)   g_Sb[idx] = sb * (1.0f / DM);
        }
    }
}

// -------------------- Kernel 2: boundary dots + softmax + prefix scan ----------
__global__ __launch_bounds__(1024) void scan_kernel(const int* __restrict__ amask)
{
    int bh = blockIdx.x;                 // 0..31
    int b  = bh >> 3;
    int h  = bh & 7;
    int t  = threadIdx.x;                // 0..1023
    int lane = t & 31, wid = t >> 5;

    __shared__ float b_sh[SEQ];
    __shared__ float wsum[32];
    __shared__ float sf_fix[8], sb_fix[8];

    // ---- tile-boundary dots from halo (warps 0..6: fwd, 8..14: bwd) ----
    if (wid < 7) {
        int mm = b*8 + wid;              // fwd at token t=128*wid+127
        float acc = 0.f;
        #pragma unroll
        for (int d = lane; d < DQ; d += 32)
            acc += g_qL[(h*NTILE + mm)*DQ + d] * g_kF[(h*NTILE + mm + 1)*DQ + d];
        #pragma unroll
        for (int off = 16; off; off >>= 1) acc += __shfl_down_sync(0xffffffffu, acc, off);
        if (lane == 0) sf_fix[wid] = acc * (1.0f / DM);
    } else if (wid >= 8 && wid < 15) {
        int j = wid - 7;                 // bwd at token t=128*j
        int mm = b*8 + j;
        float acc = 0.f;
        #pragma unroll
        for (int d = lane; d < DQ; d += 32)
            acc += g_qF[(h*NTILE + mm)*DQ + d] * g_kL[(h*NTILE + mm - 1)*DQ + d];
        #pragma unroll
        for (int off = 16; off; off >>= 1) acc += __shfl_down_sync(0xffffffffu, acc, off);
        if (lane == 0) sb_fix[j] = acc * (1.0f / DM);
    }
    __syncthreads();

    float sf = g_Sf[bh*SEQ + t];
    float sb = g_Sb[bh*SEQ + t];
    if ((t & 127) == 127 && t < SEQ-1) sf = sf_fix[t >> 7];
    if ((t & 127) == 0   && t > 0)     sb = sb_fix[t >> 7];

    bool vf = (t < SEQ-1) && (amask[b*SEQ + t + 1] != 0);
    bool vb = (t > 0)     && (amask[b*SEQ + t - 1] != 0);

    float a, bb;
    if (vf | vb) {
        float mx = fmaxf(vf ? sf : -3.4e38f, vb ? sb : -3.4e38f);
        float ea = vf ? __expf(sf - mx) : 0.f;
        float eb = vb ? __expf(sb - mx) : 0.f;
        float den = ea + eb;
        a  = ea / den;
        bb = eb / den;
    } else {
        a = bb = 1.0f / SEQ;
    }
    b_sh[t] = bb;
    __syncthreads();

    float g = 0.f;
    if (t < SEQ-1) {
        float ph = sqrtf(a * b_sh[t+1] + 1e-9f);
        g_band[bh*SEQ + t] = ph;
        g = logf(ph + 1e-9f);
    }

    float incl = g;
    #pragma unroll
    for (int off = 1; off < 32; off <<= 1) {
        float n = __shfl_up_sync(0xffffffffu, incl, off);
        if (lane >= off) incl += n;
    }
    if (lane == 31) wsum[wid] = incl;
    __syncthreads();
    if (wid == 0) {
        float w = wsum[lane];
        #pragma unroll
        for (int off = 1; off < 32; off <<= 1) {
            float n = __shfl_up_sync(0xffffffffu, w, off);
            if (lane >= off) w += n;
        }
        wsum[lane] = w;
    }
    __syncthreads();
    float base = (wid > 0) ? wsum[wid-1] : 0.f;
    g_G[bh*SEQ + t] = base + incl - g;   // exclusive prefix: G[k] = sum_{j<k} g_j
}

// -------------------- Kernel 3: materialize outputs (8 rows per block) ---------
__global__ __launch_bounds__(256) void out_kernel(float* __restrict__ out, int write_ph)
{
    const float SQRT_EPS = 3.1622776601683795e-5f;
    const float EPS = 1e-9f;

    int blk = blockIdx.x;                // bh*128 + rowTile
    int bh  = blk >> 7;
    int r0  = (blk & 127) << 3;          // first row i of 8
    int k0  = threadIdx.x << 2;

    const float* Gp = g_G + bh*SEQ;

    __shared__ float Gi_s[8];
    __shared__ float band_s[9];          // band[r0-1 .. r0+7]
    if (threadIdx.x < 8) Gi_s[threadIdx.x] = Gp[r0 + threadIdx.x];
    if (threadIdx.x < 9) {
        int ib = r0 - 1 + threadIdx.x;
        band_s[threadIdx.x] = (ib >= 0 && ib < SEQ-1) ? g_band[bh*SEQ + ib] : 0.f;
    }
    __syncthreads();

    float4 gk = *(const float4*)&Gp[k0];
    size_t base = (size_t)(bh*SEQ + r0) * SEQ + k0;
    size_t pbase = (size_t)NBH*SEQ*SEQ + base;

    #pragma unroll
    for (int r = 0; r < 8; r++) {
        int i = r0 + r;
        float Gi = Gi_s[r];
        float4 o;
        int k;
        k = k0 + 0; o.x = (k == i) ? SQRT_EPS : (__expf((k > i) ? gk.x - Gi : Gi - gk.x) + EPS);
        k = k0 + 1; o.y = (k == i) ? SQRT_EPS : (__expf((k > i) ? gk.y - Gi : Gi - gk.y) + EPS);
        k = k0 + 2; o.z = (k == i) ? SQRT_EPS : (__expf((k > i) ? gk.z - Gi : Gi - gk.z) + EPS);
        k = k0 + 3; o.w = (k == i) ? SQRT_EPS : (__expf((k > i) ? gk.w - Gi : Gi - gk.w) + EPS);
        __stcs((float4*)(out + base + (size_t)r*SEQ), o);

        if (write_ph) {
            float4 p = make_float4(SQRT_EPS, SQRT_EPS, SQRT_EPS, SQRT_EPS);
            int d = (i - 1) - k0;
            if (d >= 0 && d < 4) {
                float v = band_s[r];            // band[i-1]
                if (d == 0) p.x = v; else if (d == 1) p.y = v; else if (d == 2) p.z = v; else p.w = v;
            }
            d = (i + 1) - k0;
            if (d >= 0 && d < 4) {
                float v = band_s[r + 1];        // band[i]
                if (d == 0) p.x = v; else if (d == 1) p.y = v; else if (d == 2) p.z = v; else p.w = v;
            }
            __stcs((float4*)(out + pbase + (size_t)r*SEQ), p);
        }
    }
}

// -------------------- launch ---------------------------------------------------
extern "C" void kernel_launch(void* const* d_in, const int* in_sizes, int n_in,
                              void* d_out, int out_size)
{
    const float* ctx   = (const float*)d_in[0];   // (4,1024,512) fp32
    const int*   amask = (const int*)  d_in[1];   // (4,1024) int32
    const float* Wq    = (const float*)d_in[2];   // (512,512)
    const float* bq    = (const float*)d_in[3];   // (512,)
    const float* Wk    = (const float*)d_in[4];   // (512,512)
    const float* bk    = (const float*)d_in[5];   // (512,)
    float* out = (float*)d_out;

    long long total = (long long)NBH * SEQ * SEQ;
    int write_ph = ((long long)out_size >= 2 * total) ? 1 : 0;

    cudaFuncSetAttribute(gemm_band_kernel,
                         cudaFuncAttributeMaxDynamicSharedMemorySize, SMEM_TOTAL_GEMM);

    dim3 ggrid(NH, NTILE);               // (8, 32)
    gemm_band_kernel<<<ggrid, 256, SMEM_TOTAL_GEMM>>>(ctx, Wq, Wk, bq, bk);
    scan_kernel<<<NBH, 1024>>>(amask);
    out_kernel<<<NBH * SEQ / 8, 256>>>(out, write_ph);
}